// round 9
// baseline (speedup 1.0000x reference)
#include <cuda_runtime.h>
#include <stdint.h>

// ============================================================================
// Problem constants (fixed per reference source)
// ============================================================================
#define K_DIM 4096
#define N_DIM 4096
#define M_MAX 8192
#define HASH_MASK 0xFFFFF        // HASH_SIZE = 2^20
#define P_CONST 56598313LL       // RzLinear.P (prime), hardcoded in reference

// Scratch (device globals; no allocation allowed)
// g_A: fragment-major tf32: [M/16][K/8][32 lanes][4 words]; entry (mt,k8,lane)
//      = that thread's m16n8k8 A-fragment {a0,a1,a2,a3}.
// g_B: [K/32][16][N][2] tf32 pair-major: word ((kb*16+kp)*N + n)*2 + j
//      kp = (k%4) + 4*((k%32)/8),  j = (k%8)/4
__device__ uint32_t g_A[(size_t)M_MAX * K_DIM];
__device__ uint32_t g_B[(size_t)K_DIM * N_DIM];
__device__ int      g_rowmod[K_DIM];              // (k*r3 + r1) % P
__device__ int      g_colmod[N_DIM];              // (n*r2) % P

__device__ __forceinline__ uint32_t f32_to_tf32_rn(float f) {
    uint32_t u;
    asm("cvt.rna.tf32.f32 %0, %1;" : "=r"(u) : "f"(f));
    return u;
}
__device__ __forceinline__ uint32_t smem_u32(const void* p) {
    uint32_t a;
    asm("{ .reg .u64 t; cvta.to.shared.u64 t, %1; cvt.u32.u64 %0, t; }"
        : "=r"(a) : "l"(p));
    return a;
}
__device__ __forceinline__ void cp_async16(uint32_t dst, const void* src) {
    asm volatile("cp.async.cg.shared.global [%0], [%1], 16;"
                 :: "r"(dst), "l"(src) : "memory");
}
#define CP_COMMIT() asm volatile("cp.async.commit_group;" ::: "memory")
#define CP_WAIT2()  asm volatile("cp.async.wait_group 2;"  ::: "memory")
#define CP_WAIT0()  asm volatile("cp.async.wait_group 0;"  ::: "memory")

// m16n8k8 tf32 MMA (generic PTX, sm_80+; runs on the tensor pipe)
__device__ __forceinline__ void mma_tf32(float c[4], uint32_t a0, uint32_t a1,
                                         uint32_t a2, uint32_t a3,
                                         uint32_t b0, uint32_t b1) {
    asm volatile(
        "mma.sync.aligned.m16n8k8.row.col.f32.tf32.tf32.f32 "
        "{%0,%1,%2,%3}, {%4,%5,%6,%7}, {%8,%9}, {%0,%1,%2,%3};"
        : "+f"(c[0]), "+f"(c[1]), "+f"(c[2]), "+f"(c[3])
        : "r"(a0), "r"(a1), "r"(a2), "r"(a3), "r"(b0), "r"(b1));
}

// ============================================================================
// Kernel 1: hash residue tables (self-detects int64 vs int32 materialization)
// ============================================================================
__global__ void hash_tables_kernel(const void* __restrict__ rn_raw) {
    const long long* rn64 = (const long long*)rn_raw;
    const int*       rn32 = (const int*)rn_raw;
    long long r1, r2, r3;
    if (rn64[0] == P_CONST) { r1 = rn64[1]; r2 = rn64[2]; r3 = rn64[3]; }
    else                    { r1 = rn32[1]; r2 = rn32[2]; r3 = rn32[3]; }
    int i = blockIdx.x * blockDim.x + threadIdx.x;
    if (i < K_DIM) g_rowmod[i] = (int)(((long long)i * r3 + r1) % P_CONST);
    if (i < N_DIM) g_colmod[i] = (int)(((long long)i * r2) % P_CONST);
}

// ============================================================================
// Kernel 2: gather W into pair-major tf32 layout (unchanged)
// ============================================================================
__global__ void gather_kernel(const float* __restrict__ hw) {
    const int P = (int)P_CONST;
    const int t = blockIdx.x * blockDim.x + threadIdx.x;
    const int total = (K_DIM / 32) * 16 * (N_DIM / 2);
    if (t >= total) return;

    const int n2  = t & (N_DIM / 2 - 1);
    const int row = t >> 11;            // (kb*16 + kp)
    const int kp  = row & 15;
    const int kb  = row >> 4;
    const int k0  = kb * 32 + (kp >> 2) * 8 + (kp & 3);
    const int n   = n2 * 2;

    const int rm0 = g_rowmod[k0];
    const int rm1 = g_rowmod[k0 + 4];
    const int c0  = g_colmod[n];
    const int c1  = g_colmod[n + 1];

    int s00 = rm0 + c0; if (s00 >= P) s00 -= P;
    int s10 = rm1 + c0; if (s10 >= P) s10 -= P;
    int s01 = rm0 + c1; if (s01 >= P) s01 -= P;
    int s11 = rm1 + c1; if (s11 >= P) s11 -= P;

    uint4 w;
    w.x = f32_to_tf32_rn(__ldg(hw + (s00 & HASH_MASK)));
    w.y = f32_to_tf32_rn(__ldg(hw + (s10 & HASH_MASK)));
    w.z = f32_to_tf32_rn(__ldg(hw + (s01 & HASH_MASK)));
    w.w = f32_to_tf32_rn(__ldg(hw + (s11 & HASH_MASK)));

    ((uint4*)g_B)[t] = w;
}

// ============================================================================
// Kernel 3: x -> tf32, fragment-major permutation (unchanged)
// ============================================================================
__global__ void cvt_a_kernel(const float* __restrict__ x, int total) {
    int t = blockIdx.x * blockDim.x + threadIdx.x;
    if (t >= total) return;
    const int lane = t & 31;
    const int k8   = (t >> 5) & (K_DIM / 8 - 1);
    const int mt   = t >> (5 + 9);            // K/8 = 512 -> 9 bits
    const int lq = lane >> 2, lr = lane & 3;
    const float* xm = x + (size_t)(mt * 16) * K_DIM + k8 * 8;
    uint4 o;
    o.x = f32_to_tf32_rn(__ldg(xm + (size_t)lq * K_DIM + lr));
    o.y = f32_to_tf32_rn(__ldg(xm + (size_t)(lq + 8) * K_DIM + lr));
    o.z = f32_to_tf32_rn(__ldg(xm + (size_t)lq * K_DIM + lr + 4));
    o.w = f32_to_tf32_rn(__ldg(xm + (size_t)(lq + 8) * K_DIM + lr + 4));
    ((uint4*)g_A)[t] = o;
}

// ============================================================================
// Kernel 4: tf32 tensor-core GEMM via mma.sync
//   CTA tile 128x256, BK=32, 512 thr (16 warps 2x8 -> warp tile 64x32).
//   A: 4-stage cp.async pipeline in smem, fragment-major, 1 LDS.128/fragment.
//   B: NOT staged — LDG.64 straight from L2 (pair-major gmem layout),
//      1-deep register double buffer prefetched under the MMA burst.
//   Crossbar now carries only A (128KB LDS + 16KB STS per kt) << tensor time.
// ============================================================================
#define A_STAGE_B (128 * 32 * 4)                   // 16384, frag-major
#define STAGE_B   A_STAGE_B
#define NSTAGE 4
#define SMEM_GEMM (NSTAGE * STAGE_B)               // 65536
#define NK        (K_DIM / 32)                     // 128
#define B_STEP    (4 * N_DIM * 2)                  // +4 rows per (kt,kk) step

__device__ __forceinline__ void load_stage_a(uint32_t sbase, int stage,
                                             int m0, int kt, int tid) {
    const uint32_t a_s = sbase + stage * STAGE_B;
    // A: 32 fragment-chunks of 512B (i = mtile 0..7, j = kk 0..3);
    //    1024 x 16B transfers, 2 per thread, gmem chunk = contiguous 512B.
    #pragma unroll
    for (int p = 0; p < 2; p++) {
        const int u     = tid + p * 512;
        const int chunk = u >> 5;            // 0..31
        const int lane  = u & 31;
        const int i = chunk >> 2;            // mtile within CTA
        const int j = chunk & 3;             // kk
        const uint32_t* src = g_A +
            (((size_t)(m0 / 16 + i) * (K_DIM / 8) + (kt * 4 + j)) * 32
             + lane) * 4;
        cp_async16(a_s + u * 16, src);
    }
}

__global__ __launch_bounds__(512, 1)
void gemm_mma_kernel(const float* __restrict__ bias, float* __restrict__ C) {
    extern __shared__ char smem[];
    const uint32_t sbase = smem_u32(smem);
    const int tid  = threadIdx.x;
    const int wid  = tid >> 5;
    const int lane = tid & 31;
    const int lq = lane >> 2;     // 0..7
    const int lr = lane & 3;      // 0..3
    const int wm = wid & 1;       // 2 m-halves of 64
    const int wn = wid >> 1;      // 8 n-slices of 32

    const int m_blk = blockIdx.y * 128;
    const int n_blk = blockIdx.x * 256;

    float acc[4][4][4];
    #pragma unroll
    for (int i = 0; i < 4; i++)
        #pragma unroll
        for (int j = 0; j < 4; j++)
            #pragma unroll
            for (int r = 0; r < 4; r++) acc[i][j][r] = 0.0f;

    load_stage_a(sbase, 0, m_blk, 0, tid); CP_COMMIT();
    load_stage_a(sbase, 1, m_blk, 1, tid); CP_COMMIT();
    load_stage_a(sbase, 2, m_blk, 2, tid); CP_COMMIT();

    // B register double buffer; bp tracks the row of the LAST loaded step.
    // word((kb*16+kp)*N + n)*2 with kp=lr+4*kk -> uniform +B_STEP per step.
    const uint32_t* bp =
        g_B + ((size_t)lr * N_DIM + (n_blk + wn * 32 + lq)) * 2;
    uint2 b[2][4];
    #pragma unroll
    for (int jn = 0; jn < 4; jn++)
        b[0][jn] = __ldg((const uint2*)(bp + jn * 16));

    for (int kt = 0; kt < NK; kt++) {
        CP_WAIT2();
        __syncthreads();    // single barrier per kt (slot (kt-1)&3 drained)
        const int st = kt & (NSTAGE - 1);
        const uint32_t* As = (const uint32_t*)(smem + st * STAGE_B);
        const uint32_t* a_base = As + (wm * 16) * 128 + lane * 4;

        #pragma unroll
        for (int kk = 0; kk < 4; kk++) {
            const int cb = kk & 1;
            const int nb = cb ^ 1;
            // prefetch next step's B fragments under this burst
            {
                const uint32_t* np =
                    (kk < 3 || kt < NK - 1) ? (bp + B_STEP) : bp;
                #pragma unroll
                for (int jn = 0; jn < 4; jn++)
                    b[nb][jn] = __ldg((const uint2*)(np + jn * 16));
                bp = np;
            }
            uint4 a[4];
            #pragma unroll
            for (int im = 0; im < 4; im++)
                a[im] = *(const uint4*)(a_base + (im * 4 + kk) * 128);
            #pragma unroll
            for (int im = 0; im < 4; im++)
                #pragma unroll
                for (int jn = 0; jn < 4; jn++)
                    mma_tf32(acc[im][jn], a[im].x, a[im].y, a[im].z, a[im].w,
                             b[cb][jn].x, b[cb][jn].y);
        }

        if (kt + 3 < NK)
            load_stage_a(sbase, (kt + 3) & (NSTAGE - 1), m_blk, kt + 3, tid);
        CP_COMMIT();   // keep group count in lockstep even when empty
    }
    CP_WAIT0();

    // epilogue: bias + direct stores
    #pragma unroll
    for (int jn = 0; jn < 4; jn++) {
        const int c0 = n_blk + wn * 32 + jn * 8 + 2 * lr;
        const float bx = __ldg(bias + c0);
        const float by = __ldg(bias + c0 + 1);
        #pragma unroll
        for (int im = 0; im < 4; im++) {
            const int r0 = m_blk + wm * 64 + im * 16 + lq;
            float2 v0, v1;
            v0.x = acc[im][jn][0] + bx; v0.y = acc[im][jn][1] + by;
            v1.x = acc[im][jn][2] + bx; v1.y = acc[im][jn][3] + by;
            *(float2*)(C + (size_t)r0 * N_DIM + c0)       = v0;
            *(float2*)(C + (size_t)(r0 + 8) * N_DIM + c0) = v1;
        }
    }
}

// ============================================================================
// Host launch. Inputs routed by element count (immune to metadata ordering):
//   <=8 elems -> random_numbers; 2^20 -> hashed_weight; 4096 -> bias;
//   largest -> x. Output f32 [M, N_DIM].
// ============================================================================
extern "C" void kernel_launch(void* const* d_in, const int* in_sizes, int n_in,
                              void* d_out, int out_size) {
    const float* x = nullptr; const float* hw = nullptr;
    const void* rn = nullptr; const float* bias = nullptr;
    long long max_sz = -1; int max_i = 0;
    for (int i = 0; i < n_in; i++)
        if ((long long)in_sizes[i] > max_sz) { max_sz = in_sizes[i]; max_i = i; }
    x = (const float*)d_in[max_i];
    for (int i = 0; i < n_in; i++) {
        if (i == max_i) continue;
        if (in_sizes[i] <= 8)              rn   = d_in[i];
        else if (in_sizes[i] == (1 << 20)) hw   = (const float*)d_in[i];
        else if (in_sizes[i] == N_DIM)     bias = (const float*)d_in[i];
    }
    float* out = (float*)d_out;
    const int M = (int)(max_sz / K_DIM);   // 8192

    hash_tables_kernel<<<(K_DIM + 255) / 256, 256>>>(rn);

    const int a_total = (M / 16) * (K_DIM / 8) * 32;
    cvt_a_kernel<<<(a_total + 255) / 256, 256>>>(x, a_total);

    const int gthreads = (K_DIM / 32) * 16 * (N_DIM / 2);
    gather_kernel<<<(gthreads + 255) / 256, 256>>>(hw);

    static bool smem_set = false;
    if (!smem_set) {
        cudaFuncSetAttribute(gemm_mma_kernel,
                             cudaFuncAttributeMaxDynamicSharedMemorySize,
                             SMEM_GEMM);
        smem_set = true;
    }
    dim3 grid(N_DIM / 256, M / 128);
    gemm_mma_kernel<<<grid, 512, SMEM_GEMM>>>(bias, out);
}

// round 10
// speedup vs baseline: 2.2754x; 2.2754x over previous
#include <cuda_runtime.h>
#include <cuda_fp16.h>
#include <stdint.h>

// ============================================================================
// Problem constants (fixed per reference source)
// ============================================================================
#define K_DIM 4096
#define N_DIM 4096
#define M_MAX 8192
#define HASH_MASK 0xFFFFF        // HASH_SIZE = 2^20
#define P_CONST 56598313LL       // RzLinear.P (prime), hardcoded in reference

// Scratch (device globals; no allocation allowed)
// g_A: fragment-major fp16, [M/16][K/16][32 lanes][4 b32 words]; entry
//      (mt,k16,lane={lq*4+lr}) = m16n8k16 A-fragment:
//      w0=(m=lq,k=2lr|2lr+1) w1=(lq+8,2lr|..) w2=(lq,2lr+8|..) w3=(lq+8,2lr+8|..)
// g_B: pair-major fp16, uint2 index r*N+n with r = k16*4 + lr:
//      .x = half2(w[k0,n], w[k0+1,n]), .y = half2(w[k0+8,n], w[k0+9,n]),
//      k0 = k16*16 + 2*lr.
__device__ uint32_t g_A[(size_t)M_MAX * K_DIM / 2];
__device__ uint32_t g_B[(size_t)K_DIM * N_DIM / 2];
__device__ int      g_rowmod[K_DIM];              // (k*r3 + r1) % P
__device__ int      g_colmod[N_DIM];              // (n*r2) % P

__device__ __forceinline__ uint32_t pack_h2(float lo, float hi) {
    __half2 h = __floats2half2_rn(lo, hi);
    return *(uint32_t*)&h;
}
__device__ __forceinline__ uint32_t smem_u32(const void* p) {
    uint32_t a;
    asm("{ .reg .u64 t; cvta.to.shared.u64 t, %1; cvt.u32.u64 %0, t; }"
        : "=r"(a) : "l"(p));
    return a;
}
__device__ __forceinline__ void cp_async16(uint32_t dst, const void* src) {
    asm volatile("cp.async.cg.shared.global [%0], [%1], 16;"
                 :: "r"(dst), "l"(src) : "memory");
}
#define CP_COMMIT() asm volatile("cp.async.commit_group;" ::: "memory")
#define CP_WAIT2()  asm volatile("cp.async.wait_group 2;"  ::: "memory")
#define CP_WAIT0()  asm volatile("cp.async.wait_group 0;"  ::: "memory")

// m16n8k16 fp16 MMA, f32 accumulate (generic PTX, sm_80+)
__device__ __forceinline__ void mma_f16(float c[4], uint32_t a0, uint32_t a1,
                                        uint32_t a2, uint32_t a3,
                                        uint32_t b0, uint32_t b1) {
    asm volatile(
        "mma.sync.aligned.m16n8k16.row.col.f32.f16.f16.f32 "
        "{%0,%1,%2,%3}, {%4,%5,%6,%7}, {%8,%9}, {%0,%1,%2,%3};"
        : "+f"(c[0]), "+f"(c[1]), "+f"(c[2]), "+f"(c[3])
        : "r"(a0), "r"(a1), "r"(a2), "r"(a3), "r"(b0), "r"(b1));
}

// ============================================================================
// Kernel 1: hash residue tables (self-detects int64 vs int32 materialization)
// ============================================================================
__global__ void hash_tables_kernel(const void* __restrict__ rn_raw) {
    const long long* rn64 = (const long long*)rn_raw;
    const int*       rn32 = (const int*)rn_raw;
    long long r1, r2, r3;
    if (rn64[0] == P_CONST) { r1 = rn64[1]; r2 = rn64[2]; r3 = rn64[3]; }
    else                    { r1 = rn32[1]; r2 = rn32[2]; r3 = rn32[3]; }
    int i = blockIdx.x * blockDim.x + threadIdx.x;
    if (i < K_DIM) g_rowmod[i] = (int)(((long long)i * r3 + r1) % P_CONST);
    if (i < N_DIM) g_colmod[i] = (int)(((long long)i * r2) % P_CONST);
}

// ============================================================================
// Kernel 2: gather W into pair-major fp16 layout.
//   thread t -> uint2 at index t = r*N + n (r = k16*4 + lr):
//   4 hash gathers for k = k0, k0+1, k0+8, k0+9 at column n.
// ============================================================================
__global__ void gather_kernel(const float* __restrict__ hw) {
    const int P = (int)P_CONST;
    const int t = blockIdx.x * blockDim.x + threadIdx.x;
    const int total = (K_DIM / 4) * N_DIM;      // 1024 * 4096 uint2 entries
    if (t >= total) return;

    const int n  = t & (N_DIM - 1);
    const int r  = t >> 12;                     // k16*4 + lr
    const int lr = r & 3;
    const int k0 = (r >> 2) * 16 + 2 * lr;

    const int rm0 = g_rowmod[k0];
    const int rm1 = g_rowmod[k0 + 1];
    const int rm2 = g_rowmod[k0 + 8];
    const int rm3 = g_rowmod[k0 + 9];
    const int c   = g_colmod[n];

    int s0 = rm0 + c; if (s0 >= P) s0 -= P;
    int s1 = rm1 + c; if (s1 >= P) s1 -= P;
    int s2 = rm2 + c; if (s2 >= P) s2 -= P;
    int s3 = rm3 + c; if (s3 >= P) s3 -= P;

    const float w0 = __ldg(hw + (s0 & HASH_MASK));
    const float w1 = __ldg(hw + (s1 & HASH_MASK));
    const float w2 = __ldg(hw + (s2 & HASH_MASK));
    const float w3 = __ldg(hw + (s3 & HASH_MASK));

    uint2 o;
    o.x = pack_h2(w0, w1);
    o.y = pack_h2(w2, w3);
    ((uint2*)g_B)[t] = o;
}

// ============================================================================
// Kernel 3: x -> fp16, fragment-major permutation
//   thread t = (mt*(K/16) + k16)*32 + lane; writes one 16B fragment entry.
// ============================================================================
__global__ void cvt_a_kernel(const float* __restrict__ x, int total) {
    int t = blockIdx.x * blockDim.x + threadIdx.x;
    if (t >= total) return;
    const int lane = t & 31;
    const int k16  = (t >> 5) & (K_DIM / 16 - 1);
    const int mt   = t >> (5 + 8);            // K/16 = 256 -> 8 bits
    const int lq = lane >> 2, lr = lane & 3;
    const float* xm = x + (size_t)(mt * 16) * K_DIM + k16 * 16;
    const float2 p0 = *(const float2*)(xm + (size_t)lq * K_DIM + 2 * lr);
    const float2 p1 = *(const float2*)(xm + (size_t)(lq + 8) * K_DIM + 2 * lr);
    const float2 p2 = *(const float2*)(xm + (size_t)lq * K_DIM + 2 * lr + 8);
    const float2 p3 = *(const float2*)(xm + (size_t)(lq + 8) * K_DIM + 2 * lr + 8);
    uint4 o;
    o.x = pack_h2(p0.x, p0.y);
    o.y = pack_h2(p1.x, p1.y);
    o.z = pack_h2(p2.x, p2.y);
    o.w = pack_h2(p3.x, p3.y);
    ((uint4*)g_A)[t] = o;
}

// ============================================================================
// Kernel 4: fp16 tensor-core GEMM via mma.sync m16n8k16
//   CTA tile 128x256, BK=32 (2 k16-steps), 512 thr (16 warps 2x8 ->
//   warp tile 64x32), 4-stage cp.async pipeline, ONE __syncthreads per kt.
//   A fragments: 1x LDS.128 (fragment-major, conflict-free by construction).
//   B fragments: 1x LDS.64 (pair-major, SB_W=520 ≡ 8 mod 32 words).
// ============================================================================
#define SB_W 520
#define A_STAGE_B (8 * 2 * 32 * 16)                // 8192  (8 mtiles x 2 ks)
#define B_STAGE_B (8 * SB_W * 4)                   // 16640 (8 rows)
#define STAGE_B   (A_STAGE_B + B_STAGE_B)          // 24832
#define NSTAGE 4
#define SMEM_GEMM (NSTAGE * STAGE_B)               // 99328
#define NK        (K_DIM / 32)                     // 128

__device__ __forceinline__ void load_stage(uint32_t sbase, int stage,
                                           int m0, int n0, int kt, int tid) {
    const uint32_t a_s = sbase + stage * STAGE_B;
    const uint32_t b_s = a_s + A_STAGE_B;
    // A: 16 fragment-chunks of 512B (i = mtile 0..7, j = kstep 0..1);
    //    512 x 16B transfers, 1 per thread, gmem chunk contiguous.
    {
        const int chunk = tid >> 5;          // 0..15
        const int lane  = tid & 31;
        const int i = chunk >> 1;            // mtile within CTA
        const int j = chunk & 1;             // kstep
        const uint32_t* src = g_A +
            (((size_t)(m0 / 16 + i) * (K_DIM / 16) + (kt * 2 + j)) * 32
             + lane) * 4;
        cp_async16(a_s + tid * 16, src);
    }
    // B: 8 rows x 512 words (128 x 16B chunks per row); 2 per thread.
    #pragma unroll
    for (int p = 0; p < 2; p++) {
        const int u = tid + p * 512;
        const int r = u >> 7;                // 0..7
        const int c = u & 127;
        const uint32_t* src =
            g_B + ((size_t)(kt * 8 + r) * N_DIM + n0) * 2 + c * 4;
        cp_async16(b_s + r * (SB_W * 4) + c * 16, src);
    }
}

__global__ __launch_bounds__(512, 1)
void gemm_mma_kernel(const float* __restrict__ bias, float* __restrict__ C) {
    extern __shared__ char smem[];
    const uint32_t sbase = smem_u32(smem);
    const int tid  = threadIdx.x;
    const int wid  = tid >> 5;
    const int lane = tid & 31;
    const int lq = lane >> 2;     // 0..7
    const int lr = lane & 3;      // 0..3
    const int wm = wid & 1;       // 2 m-halves of 64
    const int wn = wid >> 1;      // 8 n-slices of 32

    const int m_blk = blockIdx.y * 128;
    const int n_blk = blockIdx.x * 256;

    float acc[4][4][4];
    #pragma unroll
    for (int i = 0; i < 4; i++)
        #pragma unroll
        for (int j = 0; j < 4; j++)
            #pragma unroll
            for (int r = 0; r < 4; r++) acc[i][j][r] = 0.0f;

    load_stage(sbase, 0, m_blk, n_blk, 0, tid); CP_COMMIT();
    load_stage(sbase, 1, m_blk, n_blk, 1, tid); CP_COMMIT();
    load_stage(sbase, 2, m_blk, n_blk, 2, tid); CP_COMMIT();

    for (int kt = 0; kt < NK; kt++) {
        CP_WAIT2();
        __syncthreads();    // single barrier per kt (slot (kt-1)&3 drained)
        const int st = kt & (NSTAGE - 1);
        const uint32_t* As = (const uint32_t*)(smem + st * STAGE_B);
        const uint32_t* Bs = (const uint32_t*)(smem + st * STAGE_B + A_STAGE_B);

        const uint32_t* a_base = As + (wm * 8) * 128 + lane * 4;
        const uint32_t* b_base = Bs + (wn * 32 + lq) * 2;

        #pragma unroll
        for (int ks = 0; ks < 2; ks++) {
            uint4 a[4];
            #pragma unroll
            for (int im = 0; im < 4; im++)
                a[im] = *(const uint4*)(a_base + (im * 2 + ks) * 128);
            uint2 b[4];
            #pragma unroll
            for (int jn = 0; jn < 4; jn++)
                b[jn] = *(const uint2*)
                    (b_base + (ks * 4 + lr) * SB_W + jn * 16);
            #pragma unroll
            for (int im = 0; im < 4; im++)
                #pragma unroll
                for (int jn = 0; jn < 4; jn++)
                    mma_f16(acc[im][jn], a[im].x, a[im].y, a[im].z, a[im].w,
                            b[jn].x, b[jn].y);
        }

        if (kt + 3 < NK)
            load_stage(sbase, (kt + 3) & (NSTAGE - 1), m_blk, n_blk,
                       kt + 3, tid);
        CP_COMMIT();   // keep group count in lockstep even when empty
    }
    CP_WAIT0();

    // epilogue: bias + direct stores (C fragment layout identical to tf32 k8)
    #pragma unroll
    for (int jn = 0; jn < 4; jn++) {
        const int c0 = n_blk + wn * 32 + jn * 8 + 2 * lr;
        const float bx = __ldg(bias + c0);
        const float by = __ldg(bias + c0 + 1);
        #pragma unroll
        for (int im = 0; im < 4; im++) {
            const int r0 = m_blk + wm * 64 + im * 16 + lq;
            float2 v0, v1;
            v0.x = acc[im][jn][0] + bx; v0.y = acc[im][jn][1] + by;
            v1.x = acc[im][jn][2] + bx; v1.y = acc[im][jn][3] + by;
            *(float2*)(C + (size_t)r0 * N_DIM + c0)       = v0;
            *(float2*)(C + (size_t)(r0 + 8) * N_DIM + c0) = v1;
        }
    }
}

// ============================================================================
// Host launch. Inputs routed by element count (immune to metadata ordering):
//   <=8 elems -> random_numbers; 2^20 -> hashed_weight; 4096 -> bias;
//   largest -> x. Output f32 [M, N_DIM].
// ============================================================================
extern "C" void kernel_launch(void* const* d_in, const int* in_sizes, int n_in,
                              void* d_out, int out_size) {
    const float* x = nullptr; const float* hw = nullptr;
    const void* rn = nullptr; const float* bias = nullptr;
    long long max_sz = -1; int max_i = 0;
    for (int i = 0; i < n_in; i++)
        if ((long long)in_sizes[i] > max_sz) { max_sz = in_sizes[i]; max_i = i; }
    x = (const float*)d_in[max_i];
    for (int i = 0; i < n_in; i++) {
        if (i == max_i) continue;
        if (in_sizes[i] <= 8)              rn   = d_in[i];
        else if (in_sizes[i] == (1 << 20)) hw   = (const float*)d_in[i];
        else if (in_sizes[i] == N_DIM)     bias = (const float*)d_in[i];
    }
    float* out = (float*)d_out;
    const int M = (int)(max_sz / K_DIM);   // 8192

    hash_tables_kernel<<<(K_DIM + 255) / 256, 256>>>(rn);

    const int a_total = (M / 16) * (K_DIM / 16) * 32;
    cvt_a_kernel<<<(a_total + 255) / 256, 256>>>(x, a_total);

    const int gtotal = (K_DIM / 4) * N_DIM;
    gather_kernel<<<(gtotal + 255) / 256, 256>>>(hw);

    static bool smem_set = false;
    if (!smem_set) {
        cudaFuncSetAttribute(gemm_mma_kernel,
                             cudaFuncAttributeMaxDynamicSharedMemorySize,
                             SMEM_GEMM);
        smem_set = true;
    }
    dim3 grid(N_DIM / 256, M / 128);
    gemm_mma_kernel<<<grid, 512, SMEM_GEMM>>>(bias, out);
}